// round 1
// baseline (speedup 1.0000x reference)
#include <cuda_runtime.h>
#include <math.h>

#define D_HID 128
#define MAX_G 16384
#define NTHREADS 128

// Scratch (allocation-free rule: __device__ globals)
__device__ float g_S[(size_t)MAX_G * D_HID];   // 8 MB: S_abs per group
__device__ float g_Wa[MAX_G];                   // sum |w| per group
__device__ float g_Ws[MAX_G];                   // sum w per group
__device__ int   g_off[MAX_G + 1];              // group start offsets

// ---------------------------------------------------------------------------
// Kernel 0: exclusive prefix sum over port_len -> g_off  (single block)
// ---------------------------------------------------------------------------
__global__ void scan_offsets_kernel(const int* __restrict__ port_len, int G) {
    __shared__ int part[512];
    const int tid = threadIdx.x;                  // 512 threads
    const int per = (G + 511) / 512;

    int s = 0;
    for (int i = 0; i < per; i++) {
        int idx = tid * per + i;
        if (idx < G) s += port_len[idx];
    }
    part[tid] = s;
    __syncthreads();
    // Hillis-Steele inclusive scan over 512 partials
    for (int off = 1; off < 512; off <<= 1) {
        int v = (tid >= off) ? part[tid - off] : 0;
        __syncthreads();
        part[tid] += v;
        __syncthreads();
    }
    int base = (tid == 0) ? 0 : part[tid - 1];
    int run = 0;
    for (int i = 0; i < per; i++) {
        int idx = tid * per + i;
        if (idx < G) {
            g_off[idx] = base + run;
            run += port_len[idx];
        }
    }
    if (tid == 511) g_off[G] = part[511];
}

// ---------------------------------------------------------------------------
// Kernel 1: per-group segment reduction.
//   S_abs[g][d] = sum_lines |w| * H[node][d] ; W_abs[g]; W_sgn[g]
// One block (128 threads, thread = d) per group. H gather is L2-resident.
// ---------------------------------------------------------------------------
__global__ void __launch_bounds__(NTHREADS)
seg_reduce_kernel(const float* __restrict__ H,
                  const float* __restrict__ w,
                  const int*   __restrict__ nodes) {
    const int g   = blockIdx.x;
    const int tid = threadIdx.x;
    const int start = g_off[g];
    const int end   = g_off[g + 1];

    __shared__ float sw[NTHREADS];
    __shared__ int   sn[NTHREADS];

    float acc0 = 0.f, acc1 = 0.f, acc2 = 0.f, acc3 = 0.f;
    float wa = 0.f, ws = 0.f;

    for (int base = start; base < end; base += NTHREADS) {
        const int cnt = min(NTHREADS, end - base);
        if (tid < cnt) {
            float ww = w[base + tid];
            ws += ww;
            float wwa = fabsf(ww);
            wa += wwa;
            sw[tid] = wwa;
            sn[tid] = nodes[base + tid];
        }
        __syncthreads();
        int j = 0;
        for (; j + 4 <= cnt; j += 4) {
            acc0 += sw[j + 0] * H[(size_t)sn[j + 0] * D_HID + tid];
            acc1 += sw[j + 1] * H[(size_t)sn[j + 1] * D_HID + tid];
            acc2 += sw[j + 2] * H[(size_t)sn[j + 2] * D_HID + tid];
            acc3 += sw[j + 3] * H[(size_t)sn[j + 3] * D_HID + tid];
        }
        for (; j < cnt; j++)
            acc0 += sw[j] * H[(size_t)sn[j] * D_HID + tid];
        __syncthreads();
    }

    g_S[(size_t)g * D_HID + tid] = (acc0 + acc1) + (acc2 + acc3);

    // block-reduce the scalar weight sums
    __shared__ float rwa[NTHREADS], rws[NTHREADS];
    rwa[tid] = wa; rws[tid] = ws;
    __syncthreads();
    for (int off = NTHREADS / 2; off > 0; off >>= 1) {
        if (tid < off) { rwa[tid] += rwa[tid + off]; rws[tid] += rws[tid + off]; }
        __syncthreads();
    }
    if (tid == 0) { g_Wa[g] = rwa[0]; g_Ws[g] = rws[0]; }
}

// ---------------------------------------------------------------------------
// Kernel 2: per-sample LOO correction + L2 normalize. One block per sample.
// ---------------------------------------------------------------------------
__global__ void __launch_bounds__(NTHREADS)
sample_kernel(const float* __restrict__ H,
              const float* __restrict__ w,
              const int*   __restrict__ nodes,
              const int*   __restrict__ anchor_idx,
              const int*   __restrict__ pf_gid,
              float*       __restrict__ out,
              int B, int G) {
    const int b   = blockIdx.x;
    const int tid = threadIdx.x;

    const int g = pf_gid[b];
    const bool valid = (g >= 0) && (g < G);
    const int gc = min(max(g, 0), G - 1);
    const int anchor = anchor_idx[b];
    const int start = g_off[gc];
    const int end   = g_off[gc + 1];

    // leave-one-out self weight: sum of w over lines matching (gc, anchor)
    float swa = 0.f, sws = 0.f;
    for (int i = start + tid; i < end; i += NTHREADS) {
        if (nodes[i] == anchor) {
            float ww = w[i];
            swa += fabsf(ww);
            sws += ww;
        }
    }
    __shared__ float ra[NTHREADS], rs[NTHREADS];
    ra[tid] = swa; rs[tid] = sws;
    __syncthreads();
    for (int off = NTHREADS / 2; off > 0; off >>= 1) {
        if (tid < off) { ra[tid] += ra[tid + off]; rs[tid] += rs[tid + off]; }
        __syncthreads();
    }
    swa = ra[0]; sws = rs[0];
    __syncthreads();   // done reading ra/rs before reuse

    const float ha  = H[(size_t)anchor * D_HID + tid];
    const float sab = g_S[(size_t)gc * D_HID + tid];
    const float denom = fmaxf(g_Wa[gc] - swa, 1e-12f);

    float v = (sab - swa * ha) / denom;
    float s = (g_Ws[gc] - sws) / denom;
    if (!valid) { v = 0.f; s = 0.f; }
    float vs = s * v;

    // norms of both vectors in one pass
    ra[tid] = v * v; rs[tid] = vs * vs;
    __syncthreads();
    for (int off = NTHREADS / 2; off > 0; off >>= 1) {
        if (tid < off) { ra[tid] += ra[tid + off]; rs[tid] += rs[tid + off]; }
        __syncthreads();
    }
    const float na = sqrtf(ra[0]);
    const float ns = sqrtf(rs[0]);

    const float oa = v / fmaxf(na, 1e-6f);
    const float os = (ns > 0.f) ? vs / fmaxf(ns, 1e-6f) : vs;

    out[(size_t)b * D_HID + tid] = oa;
    out[(size_t)B * D_HID + (size_t)b * D_HID + tid] = os;
}

// ---------------------------------------------------------------------------
extern "C" void kernel_launch(void* const* d_in, const int* in_sizes, int n_in,
                              void* d_out, int out_size) {
    const float* H      = (const float*)d_in[0];   // [N, 128]
    const float* w      = (const float*)d_in[1];   // [L]
    const int*   anchor = (const int*)  d_in[2];   // [B]
    const int*   pfgid  = (const int*)  d_in[3];   // [B]
    const int*   nodes  = (const int*)  d_in[4];   // [L]
    const int*   plen   = (const int*)  d_in[5];   // [G]
    float* out = (float*)d_out;                    // [2, B, 128]

    const int B = in_sizes[2];
    const int G = in_sizes[5];

    scan_offsets_kernel<<<1, 512>>>(plen, G);
    seg_reduce_kernel<<<G, NTHREADS>>>(H, w, nodes);
    sample_kernel<<<B, NTHREADS>>>(H, w, nodes, anchor, pfgid, out, B, G);
}

// round 2
// speedup vs baseline: 1.5932x; 1.5932x over previous
#include <cuda_runtime.h>
#include <math.h>

#define D_HID   128
#define MAX_G   16384
#define NT      128
#define SCAN_BS 128   // elements per scan chunk
#define MAX_CHUNKS 512

// Scratch (allocation-free rule: __device__ globals)
__device__ int g_part[MAX_CHUNKS];
__device__ int g_off[MAX_G + 1];

// ---------------------------------------------------------------------------
// Scan kernel A: per-chunk sums of port_len (coalesced)
// ---------------------------------------------------------------------------
__global__ void chunk_sum_kernel(const int* __restrict__ plen, int G) {
    const int blk = blockIdx.x, tid = threadIdx.x;
    const int idx = blk * SCAN_BS + tid;
    __shared__ int s[SCAN_BS];
    s[tid] = (idx < G) ? plen[idx] : 0;
    __syncthreads();
    for (int off = SCAN_BS / 2; off > 0; off >>= 1) {
        if (tid < off) s[tid] += s[tid + off];
        __syncthreads();
    }
    if (tid == 0) g_part[blk] = s[0];
}

// ---------------------------------------------------------------------------
// Scan kernel B: each chunk computes its base from g_part, scans its 128
// elements in smem, writes exclusive offsets (coalesced).
// ---------------------------------------------------------------------------
__global__ void write_off_kernel(const int* __restrict__ plen, int G, int nblk) {
    const int blk = blockIdx.x, tid = threadIdx.x;
    __shared__ int parts[MAX_CHUNKS];
    for (int i = tid; i < nblk; i += SCAN_BS) parts[i] = g_part[i];
    __syncthreads();
    __shared__ int sbase;
    if (tid == 0) {
        int b = 0;
        for (int k = 0; k < blk; k++) b += parts[k];
        sbase = b;
    }
    __syncthreads();
    const int base = sbase;

    const int idx = blk * SCAN_BS + tid;
    const int v = (idx < G) ? plen[idx] : 0;
    __shared__ int sc[SCAN_BS];
    sc[tid] = v;
    __syncthreads();
    for (int off = 1; off < SCAN_BS; off <<= 1) {
        int t = (tid >= off) ? sc[tid - off] : 0;
        __syncthreads();
        sc[tid] += t;
        __syncthreads();
    }
    if (idx < G)      g_off[idx] = base + sc[tid] - v;  // exclusive
    if (idx == G - 1) g_off[G]   = base + sc[tid];      // total
}

// ---------------------------------------------------------------------------
// Fused kernel: one block (128 threads, thread = d) per sample.
// Computes the group's weighted H-sum, total weights, anchor self-weights,
// LOO correction, and L2 normalization — all in one pass over the group.
// ---------------------------------------------------------------------------
__global__ void __launch_bounds__(NT)
fused_kernel(const float* __restrict__ H,
             const float* __restrict__ w,
             const int*   __restrict__ nodes,
             const int*   __restrict__ anchor_idx,
             const int*   __restrict__ pf_gid,
             float*       __restrict__ out,
             int B, int G) {
    const int b   = blockIdx.x;
    const int tid = threadIdx.x;

    const int g = pf_gid[b];
    const bool valid = (g >= 0) && (g < G);
    const int gc = min(max(g, 0), G - 1);
    const int anchor = anchor_idx[b];
    const int start = g_off[gc];
    const int end   = g_off[gc + 1];

    __shared__ float sw[NT];
    __shared__ int   sn[NT];

    float a0=0.f,a1=0.f,a2=0.f,a3=0.f,a4=0.f,a5=0.f,a6=0.f,a7=0.f;
    float wa = 0.f, ws = 0.f, swa = 0.f, sws = 0.f;

    for (int base = start; base < end; base += NT) {
        const int cnt = min(NT, end - base);
        if (tid < cnt) {
            const float ww  = w[base + tid];
            const int   nd  = nodes[base + tid];
            const float wwa = fabsf(ww);
            ws += ww; wa += wwa;
            if (nd == anchor) { swa += wwa; sws += ww; }
            sw[tid] = wwa;
            sn[tid] = nd;
        }
        __syncthreads();
        int j = 0;
        for (; j + 8 <= cnt; j += 8) {
            a0 += sw[j+0] * H[(size_t)sn[j+0] * D_HID + tid];
            a1 += sw[j+1] * H[(size_t)sn[j+1] * D_HID + tid];
            a2 += sw[j+2] * H[(size_t)sn[j+2] * D_HID + tid];
            a3 += sw[j+3] * H[(size_t)sn[j+3] * D_HID + tid];
            a4 += sw[j+4] * H[(size_t)sn[j+4] * D_HID + tid];
            a5 += sw[j+5] * H[(size_t)sn[j+5] * D_HID + tid];
            a6 += sw[j+6] * H[(size_t)sn[j+6] * D_HID + tid];
            a7 += sw[j+7] * H[(size_t)sn[j+7] * D_HID + tid];
        }
        for (; j < cnt; j++)
            a0 += sw[j] * H[(size_t)sn[j] * D_HID + tid];
        __syncthreads();
    }
    const float acc = ((a0 + a1) + (a2 + a3)) + ((a4 + a5) + (a6 + a7));

    // Block-reduce the four scalar sums
    __shared__ float r0[NT], r1[NT], r2[NT], r3[NT];
    r0[tid] = wa; r1[tid] = ws; r2[tid] = swa; r3[tid] = sws;
    __syncthreads();
    for (int off = NT / 2; off > 0; off >>= 1) {
        if (tid < off) {
            r0[tid] += r0[tid + off];
            r1[tid] += r1[tid + off];
            r2[tid] += r2[tid + off];
            r3[tid] += r3[tid + off];
        }
        __syncthreads();
    }
    wa = r0[0]; ws = r1[0]; swa = r2[0]; sws = r3[0];
    __syncthreads();

    const float ha    = H[(size_t)anchor * D_HID + tid];
    const float denom = fmaxf(wa - swa, 1e-12f);

    float v = (acc - swa * ha) / denom;
    float s = (ws - sws) / denom;
    if (!valid) { v = 0.f; s = 0.f; }
    const float vs = s * v;

    // Norms of both vectors
    r0[tid] = v * v; r1[tid] = vs * vs;
    __syncthreads();
    for (int off = NT / 2; off > 0; off >>= 1) {
        if (tid < off) { r0[tid] += r0[tid + off]; r1[tid] += r1[tid + off]; }
        __syncthreads();
    }
    const float na = sqrtf(r0[0]);
    const float ns = sqrtf(r1[0]);

    out[(size_t)b * D_HID + tid] = v / fmaxf(na, 1e-6f);
    out[(size_t)(B + b) * D_HID + tid] = (ns > 0.f) ? vs / fmaxf(ns, 1e-6f) : vs;
}

// ---------------------------------------------------------------------------
extern "C" void kernel_launch(void* const* d_in, const int* in_sizes, int n_in,
                              void* d_out, int out_size) {
    const float* H      = (const float*)d_in[0];   // [N, 128]
    const float* w      = (const float*)d_in[1];   // [L]
    const int*   anchor = (const int*)  d_in[2];   // [B]
    const int*   pfgid  = (const int*)  d_in[3];   // [B]
    const int*   nodes  = (const int*)  d_in[4];   // [L]
    const int*   plen   = (const int*)  d_in[5];   // [G]
    float* out = (float*)d_out;                    // [2, B, 128]

    const int B = in_sizes[2];
    const int G = in_sizes[5];
    const int nblk = (G + SCAN_BS - 1) / SCAN_BS;

    chunk_sum_kernel<<<nblk, SCAN_BS>>>(plen, G);
    write_off_kernel<<<nblk, SCAN_BS>>>(plen, G, nblk);
    fused_kernel<<<B, NT>>>(H, w, nodes, anchor, pfgid, out, B, G);
}